// round 12
// baseline (speedup 1.0000x reference)
#include <cuda_runtime.h>
#include <cuda_bf16.h>
#include <cstdint>

// Dynamics_40510131536026: LSTM encoder (T=64) + autoregressive decoder (T=64)
// B=65536, HID=32, fp32. One thread per batch element. FFMA2 (fma.rn.f32x2)
// packed over the K dimension of each dot product; weights pre-packed in shared
// memory so each LDS.128 yields two f32x2 operands (broadcast, conflict-free).
// R11 fix: gate-row loop NOT unrolled (ptxas load-hoisting over the previous
// 2300-instr straight-line body caused multi-KB local spill under the 128-reg
// cap). c-state and h_new staging stay in per-thread smem slots.

#define THREADS 128
#define HID 32
#define T_ENC 64

typedef unsigned long long u64;

__device__ __forceinline__ u64 fma2(u64 a, u64 b, u64 c) {
    u64 d;
    asm("fma.rn.f32x2 %0, %1, %2, %3;" : "=l"(d) : "l"(a), "l"(b), "l"(c));
    return d;
}
__device__ __forceinline__ u64 pack2(float lo, float hi) {
    u64 r;
    asm("mov.b64 %0, {%1, %2};" : "=l"(r) : "f"(lo), "f"(hi));
    return r;
}
__device__ __forceinline__ float hsum2(u64 v) {
    float lo, hi;
    asm("mov.b64 {%0, %1}, %2;" : "=f"(lo), "=f"(hi) : "l"(v));
    return lo + hi;
}
__device__ __forceinline__ float sigm(float x) {
    return __fdividef(1.0f, 1.0f + __expf(-x));
}
__device__ __forceinline__ float tanhx(float x) {
    return __fdividef(2.0f, 1.0f + __expf(-2.0f * x)) - 1.0f;
}

// Dynamic smem layout:
//   sWhh : 32*16*2 float4 = 16384 B
//   sWih : 32*2*2  float4 =  2048 B
//   sWd  : 16      float4 =   256 B
//   sHn  : 16*128  u64    = 16384 B   (h_new staging, per-thread slot)
//   sC   : 32*128  float  = 16384 B   (c state, per-thread slot)
#define SWHH_F4 (HID * 16 * 2)
#define SWIH_F4 (HID * 2 * 2)
#define SWD_F4  16
#define SMEM_BYTES ((SWHH_F4 + SWIH_F4 + SWD_F4) * 16 + 16 * THREADS * 8 + HID * THREADS * 4)

// One LSTM step. x0/x1: packed input pairs (4 floats). h2: 16 packed pairs
// (32 floats, persistent registers). c lives in sC[j*128+tid].
// The j loop is deliberately NOT unrolled (see header comment).
__device__ __forceinline__ void lstm_step(
    u64 x0, u64 x1, u64* __restrict__ h2,
    const float4* __restrict__ sWih, const float4* __restrict__ sWhh,
    u64* __restrict__ sHn, float* __restrict__ sC, int tid)
{
    float hv_prev = 0.0f;
#pragma unroll 1
    for (int j = 0; j < HID; j++) {
        u64 ai, af, ag, ao;
        {   // x @ W_ih.T contribution
            ulonglong2 w0 = *reinterpret_cast<const ulonglong2*>(&sWih[(j * 2 + 0) * 2]);
            ulonglong2 w1 = *reinterpret_cast<const ulonglong2*>(&sWih[(j * 2 + 0) * 2 + 1]);
            ai = fma2(x0, w0.x, 0ull);
            af = fma2(x0, w0.y, 0ull);
            ag = fma2(x0, w1.x, 0ull);
            ao = fma2(x0, w1.y, 0ull);
            w0 = *reinterpret_cast<const ulonglong2*>(&sWih[(j * 2 + 1) * 2]);
            w1 = *reinterpret_cast<const ulonglong2*>(&sWih[(j * 2 + 1) * 2 + 1]);
            ai = fma2(x1, w0.x, ai);
            af = fma2(x1, w0.y, af);
            ag = fma2(x1, w1.x, ag);
            ao = fma2(x1, w1.y, ao);
        }
        const float4* wrow = &sWhh[j * 16 * 2];
#pragma unroll
        for (int k2 = 0; k2 < 16; k2++) {
            ulonglong2 w0 = *reinterpret_cast<const ulonglong2*>(&wrow[k2 * 2]);
            ulonglong2 w1 = *reinterpret_cast<const ulonglong2*>(&wrow[k2 * 2 + 1]);
            u64 h = h2[k2];
            ai = fma2(h, w0.x, ai);
            af = fma2(h, w0.y, af);
            ag = fma2(h, w1.x, ag);
            ao = fma2(h, w1.y, ao);
        }
        float ii = sigm(hsum2(ai));
        float ff = sigm(hsum2(af));
        float gg = tanhx(hsum2(ag));
        float oo = sigm(hsum2(ao));
        float cn = ff * sC[j * THREADS + tid] + ii * gg;
        sC[j * THREADS + tid] = cn;
        float hj = oo * tanhx(cn);
        if (j & 1)
            sHn[(j >> 1) * THREADS + tid] = pack2(hv_prev, hj);
        else
            hv_prev = hj;
    }
#pragma unroll
    for (int k2 = 0; k2 < 16; k2++)
        h2[k2] = sHn[k2 * THREADS + tid];
}

__global__ __launch_bounds__(THREADS, 4)
void dynamics_kernel(
    const float* __restrict__ poses,   // [64, B, 4]
    const float* __restrict__ W_ih,    // [128, 4]
    const float* __restrict__ W_hh,    // [128, 32]
    const float* __restrict__ W_d,     // [3, 32]
    const int*   __restrict__ n_new,   // scalar
    float* __restrict__ out,           // [Tdec, B, 4]
    int B, int Tdec_max)
{
    extern __shared__ char smem_raw[];
    float4* sWhh = reinterpret_cast<float4*>(smem_raw);
    float4* sWih = sWhh + SWHH_F4;
    float4* sWd  = sWih + SWIH_F4;
    u64*    sHn  = reinterpret_cast<u64*>(sWd + SWD_F4);
    float*  sC   = reinterpret_cast<float*>(sHn + 16 * THREADS);

    int tid = threadIdx.x;

    // Cooperative weight packing.
    // sWhh[(j*16+k2)*2+e]: e=0 -> {Wi[j][k],Wi[j][k+1],Wf[j][k],Wf[j][k+1]},
    //                      e=1 -> {Wg..., Wo...}   (gate rows: i=0,f=1,g=2,o=3)
    for (int idx = tid; idx < SWHH_F4; idx += THREADS) {
        int e  = idx & 1;
        int k2 = (idx >> 1) & 15;
        int j  = idx >> 5;
        int g0 = 2 * e, g1 = 2 * e + 1;
        int k  = 2 * k2;
        sWhh[idx] = make_float4(
            W_hh[(g0 * HID + j) * HID + k], W_hh[(g0 * HID + j) * HID + k + 1],
            W_hh[(g1 * HID + j) * HID + k], W_hh[(g1 * HID + j) * HID + k + 1]);
    }
    for (int idx = tid; idx < SWIH_F4; idx += THREADS) {
        int e  = idx & 1;
        int m2 = (idx >> 1) & 1;
        int j  = idx >> 2;
        int g0 = 2 * e, g1 = 2 * e + 1;
        int m  = 2 * m2;
        sWih[idx] = make_float4(
            W_ih[(g0 * HID + j) * 4 + m], W_ih[(g0 * HID + j) * 4 + m + 1],
            W_ih[(g1 * HID + j) * 4 + m], W_ih[(g1 * HID + j) * 4 + m + 1]);
    }
    for (int idx = tid; idx < SWD_F4; idx += THREADS) {
        int k = 2 * idx;   // rows 1 (cs) and 2 (sn) of W_dense
        sWd[idx] = make_float4(W_d[HID + k], W_d[HID + k + 1],
                               W_d[2 * HID + k], W_d[2 * HID + k + 1]);
    }
    __syncthreads();

    int b = blockIdx.x * THREADS + tid;
    if (b >= B) return;

    u64 h2[16];
#pragma unroll
    for (int k2 = 0; k2 < 16; k2++) h2[k2] = 0ull;
#pragma unroll
    for (int j = 0; j < HID; j++) sC[j * THREADS + tid] = 0.0f;

    // ---- Encoder: 64 steps over poses ----
    float4 p = make_float4(0.f, 0.f, 0.f, 0.f);
#pragma unroll 1
    for (int t = 0; t < T_ENC; t++) {
        p = *reinterpret_cast<const float4*>(poses + ((size_t)t * B + b) * 4);
        lstm_step(pack2(p.x, p.y), pack2(p.z, p.w), h2, sWih, sWhh, sHn, sC, tid);
    }
    float px = p.x, py = p.y;  // last_pose[:, :2], constant through the decoder

    int Td = *n_new;
    if (Td > Tdec_max) Td = Tdec_max;

    // ---- Decoder ----
#pragma unroll 1
    for (int t = 0; t < Td; t++) {
        // vel components 1 (cs) and 2 (sn) from current h
        u64 ac = 0ull, as = 0ull;
#pragma unroll
        for (int k2 = 0; k2 < 16; k2++) {
            ulonglong2 w = *reinterpret_cast<const ulonglong2*>(&sWd[k2]);
            ac = fma2(h2[k2], w.x, ac);
            as = fma2(h2[k2], w.y, as);
        }
        float cs = hsum2(ac);
        float sn = hsum2(as);
        float rn;
        asm("rsqrt.approx.f32 %0, %1;" : "=f"(rn) : "f"(cs * cs + sn * sn));
        cs *= rn;
        sn *= rn;

        *reinterpret_cast<float4*>(out + ((size_t)t * B + b) * 4) =
            make_float4(px, py, cs, sn);

        if (t + 1 < Td) {  // last step's LSTM output is never consumed
            lstm_step(pack2(px, py), pack2(cs, sn), h2, sWih, sWhh, sHn, sC, tid);
        }
    }
}

extern "C" void kernel_launch(void* const* d_in, const int* in_sizes, int n_in,
                              void* d_out, int out_size) {
    const float* poses = (const float*)d_in[0];
    // d_in[1] = deltas: never read (the scan body ignores dt); only its length matters.
    const float* W_ih  = (const float*)d_in[2];
    const float* W_hh  = (const float*)d_in[3];
    const float* W_d   = (const float*)d_in[4];
    const int*   n_new = (const int*)d_in[5];
    float* out = (float*)d_out;

    int B = in_sizes[1] / 64;                      // deltas is [64, B]
    int Tdec_max = (B > 0) ? (out_size / (4 * B)) : 0;

    static bool attr_set = false;
    if (!attr_set) {
        cudaFuncSetAttribute(dynamics_kernel,
                             cudaFuncAttributeMaxDynamicSharedMemorySize, SMEM_BYTES);
        attr_set = true;
    }

    int grid = (B + THREADS - 1) / THREADS;
    dynamics_kernel<<<grid, THREADS, SMEM_BYTES>>>(
        poses, W_ih, W_hh, W_d, n_new, out, B, Tdec_max);
}

// round 13
// speedup vs baseline: 1.1686x; 1.1686x over previous
#include <cuda_runtime.h>
#include <cuda_bf16.h>
#include <cstdint>

// Dynamics_40510131536026: LSTM encoder (T=64) + autoregressive decoder (T=64)
// B=65536, HID=32, fp32. R13: TWO batch elements per thread — each broadcast
// weight LDS.128 now feeds FFMA2 work for both elements, halving per-element
// LSU traffic (R12 ncu: L1=72.5% vs fma=41.8%, LSU-bound).
// FFMA2 (fma.rn.f32x2) packed over the K dimension of every dot product;
// weights pre-packed in shared so each LDS.128 yields two f32x2 operands.
// j gate-row loop NOT unrolled (R11 lesson: straight-line body -> ptxas load
// hoisting -> catastrophic spill). __launch_bounds__(128,2): no register cap
// (256 regs avail), occupancy 2 CTAs/SM is all the 256-CTA grid needs.

#define THREADS 128
#define HID 32
#define T_ENC 64

typedef unsigned long long u64;

__device__ __forceinline__ u64 fma2(u64 a, u64 b, u64 c) {
    u64 d;
    asm("fma.rn.f32x2 %0, %1, %2, %3;" : "=l"(d) : "l"(a), "l"(b), "l"(c));
    return d;
}
__device__ __forceinline__ u64 pack2(float lo, float hi) {
    u64 r;
    asm("mov.b64 %0, {%1, %2};" : "=l"(r) : "f"(lo), "f"(hi));
    return r;
}
__device__ __forceinline__ float hsum2(u64 v) {
    float lo, hi;
    asm("mov.b64 {%0, %1}, %2;" : "=f"(lo), "=f"(hi) : "l"(v));
    return lo + hi;
}
__device__ __forceinline__ float sigm(float x) {
    return __fdividef(1.0f, 1.0f + __expf(-x));
}
__device__ __forceinline__ float tanhx(float x) {
    return __fdividef(2.0f, 1.0f + __expf(-2.0f * x)) - 1.0f;
}

// Dynamic smem layout:
//   sWhh : 32*16*2 float4 = 16384 B
//   sWih : 32*2*2  float4 =  2048 B
//   sWd  : 16      float4 =   256 B
//   sHnA/sHnB : 16*128 u64  = 16384 B each   (h_new staging, per-thread slot)
//   sCa/sCb   : 32*128 f32  = 16384 B each   (c state, per-thread slot)
#define SWHH_F4 (HID * 16 * 2)
#define SWIH_F4 (HID * 2 * 2)
#define SWD_F4  16
#define SMEM_BYTES ((SWHH_F4 + SWIH_F4 + SWD_F4) * 16 \
                    + 2 * 16 * THREADS * 8 + 2 * HID * THREADS * 4)

// One LSTM step for TWO batch elements sharing the same weight loads.
__device__ __forceinline__ void lstm_step2(
    u64 x0a, u64 x1a, u64 x0b, u64 x1b,
    u64* __restrict__ h2a, u64* __restrict__ h2b,
    const float4* __restrict__ sWih, const float4* __restrict__ sWhh,
    u64* __restrict__ sHnA, u64* __restrict__ sHnB,
    float* __restrict__ sCa, float* __restrict__ sCb, int tid)
{
    float hva = 0.0f, hvb = 0.0f;
#pragma unroll 1
    for (int j = 0; j < HID; j++) {
        u64 aia, afa, aga, aoa, aib, afb, agb, aob;
        {   // x @ W_ih.T contribution (weights loaded once, used twice)
            ulonglong2 w0 = *reinterpret_cast<const ulonglong2*>(&sWih[(j * 2 + 0) * 2]);
            ulonglong2 w1 = *reinterpret_cast<const ulonglong2*>(&sWih[(j * 2 + 0) * 2 + 1]);
            aia = fma2(x0a, w0.x, 0ull);  aib = fma2(x0b, w0.x, 0ull);
            afa = fma2(x0a, w0.y, 0ull);  afb = fma2(x0b, w0.y, 0ull);
            aga = fma2(x0a, w1.x, 0ull);  agb = fma2(x0b, w1.x, 0ull);
            aoa = fma2(x0a, w1.y, 0ull);  aob = fma2(x0b, w1.y, 0ull);
            w0 = *reinterpret_cast<const ulonglong2*>(&sWih[(j * 2 + 1) * 2]);
            w1 = *reinterpret_cast<const ulonglong2*>(&sWih[(j * 2 + 1) * 2 + 1]);
            aia = fma2(x1a, w0.x, aia);  aib = fma2(x1b, w0.x, aib);
            afa = fma2(x1a, w0.y, afa);  afb = fma2(x1b, w0.y, afb);
            aga = fma2(x1a, w1.x, aga);  agb = fma2(x1b, w1.x, agb);
            aoa = fma2(x1a, w1.y, aoa);  aob = fma2(x1b, w1.y, aob);
        }
        const float4* wrow = &sWhh[j * 16 * 2];
#pragma unroll
        for (int k2 = 0; k2 < 16; k2++) {
            ulonglong2 w0 = *reinterpret_cast<const ulonglong2*>(&wrow[k2 * 2]);
            ulonglong2 w1 = *reinterpret_cast<const ulonglong2*>(&wrow[k2 * 2 + 1]);
            u64 ha = h2a[k2];
            u64 hb = h2b[k2];
            aia = fma2(ha, w0.x, aia);  aib = fma2(hb, w0.x, aib);
            afa = fma2(ha, w0.y, afa);  afb = fma2(hb, w0.y, afb);
            aga = fma2(ha, w1.x, aga);  agb = fma2(hb, w1.x, agb);
            aoa = fma2(ha, w1.y, aoa);  aob = fma2(hb, w1.y, aob);
        }
        // Element A epilogue
        {
            float ii = sigm(hsum2(aia));
            float ff = sigm(hsum2(afa));
            float gg = tanhx(hsum2(aga));
            float oo = sigm(hsum2(aoa));
            float cn = ff * sCa[j * THREADS + tid] + ii * gg;
            sCa[j * THREADS + tid] = cn;
            float hj = oo * tanhx(cn);
            if (j & 1) sHnA[(j >> 1) * THREADS + tid] = pack2(hva, hj);
            else       hva = hj;
        }
        // Element B epilogue
        {
            float ii = sigm(hsum2(aib));
            float ff = sigm(hsum2(afb));
            float gg = tanhx(hsum2(agb));
            float oo = sigm(hsum2(aob));
            float cn = ff * sCb[j * THREADS + tid] + ii * gg;
            sCb[j * THREADS + tid] = cn;
            float hj = oo * tanhx(cn);
            if (j & 1) sHnB[(j >> 1) * THREADS + tid] = pack2(hvb, hj);
            else       hvb = hj;
        }
    }
#pragma unroll
    for (int k2 = 0; k2 < 16; k2++) {
        h2a[k2] = sHnA[k2 * THREADS + tid];
        h2b[k2] = sHnB[k2 * THREADS + tid];
    }
}

__global__ __launch_bounds__(THREADS, 2)
void dynamics_kernel(
    const float* __restrict__ poses,   // [64, B, 4]
    const float* __restrict__ W_ih,    // [128, 4]
    const float* __restrict__ W_hh,    // [128, 32]
    const float* __restrict__ W_d,     // [3, 32]
    const int*   __restrict__ n_new,   // scalar
    float* __restrict__ out,           // [Tdec, B, 4]
    int B, int Bh, int Tdec_max)
{
    extern __shared__ char smem_raw[];
    float4* sWhh = reinterpret_cast<float4*>(smem_raw);
    float4* sWih = sWhh + SWHH_F4;
    float4* sWd  = sWih + SWIH_F4;
    u64*    sHnA = reinterpret_cast<u64*>(sWd + SWD_F4);
    u64*    sHnB = sHnA + 16 * THREADS;
    float*  sCa  = reinterpret_cast<float*>(sHnB + 16 * THREADS);
    float*  sCb  = sCa + HID * THREADS;

    int tid = threadIdx.x;

    // Cooperative weight packing.
    // sWhh[(j*16+k2)*2+e]: e=0 -> {Wi[j][k],Wi[j][k+1],Wf[j][k],Wf[j][k+1]},
    //                      e=1 -> {Wg..., Wo...}   (gate rows: i=0,f=1,g=2,o=3)
    for (int idx = tid; idx < SWHH_F4; idx += THREADS) {
        int e  = idx & 1;
        int k2 = (idx >> 1) & 15;
        int j  = idx >> 5;
        int g0 = 2 * e, g1 = 2 * e + 1;
        int k  = 2 * k2;
        sWhh[idx] = make_float4(
            W_hh[(g0 * HID + j) * HID + k], W_hh[(g0 * HID + j) * HID + k + 1],
            W_hh[(g1 * HID + j) * HID + k], W_hh[(g1 * HID + j) * HID + k + 1]);
    }
    for (int idx = tid; idx < SWIH_F4; idx += THREADS) {
        int e  = idx & 1;
        int m2 = (idx >> 1) & 1;
        int j  = idx >> 2;
        int g0 = 2 * e, g1 = 2 * e + 1;
        int m  = 2 * m2;
        sWih[idx] = make_float4(
            W_ih[(g0 * HID + j) * 4 + m], W_ih[(g0 * HID + j) * 4 + m + 1],
            W_ih[(g1 * HID + j) * 4 + m], W_ih[(g1 * HID + j) * 4 + m + 1]);
    }
    for (int idx = tid; idx < SWD_F4; idx += THREADS) {
        int k = 2 * idx;   // rows 1 (cs) and 2 (sn) of W_dense
        sWd[idx] = make_float4(W_d[HID + k], W_d[HID + k + 1],
                               W_d[2 * HID + k], W_d[2 * HID + k + 1]);
    }
    __syncthreads();

    int b0 = blockIdx.x * THREADS + tid;
    if (b0 >= Bh) return;
    int b1 = b0 + Bh;
    bool vb = (b1 < B);
    int b1c = vb ? b1 : b0;   // clamp: redundant compute, stores guarded

    u64 h2a[16], h2b[16];
#pragma unroll
    for (int k2 = 0; k2 < 16; k2++) { h2a[k2] = 0ull; h2b[k2] = 0ull; }
#pragma unroll
    for (int j = 0; j < HID; j++) {
        sCa[j * THREADS + tid] = 0.0f;
        sCb[j * THREADS + tid] = 0.0f;
    }

    // ---- Encoder: 64 steps over poses ----
    float4 pa = make_float4(0.f, 0.f, 0.f, 0.f);
    float4 pb = pa;
#pragma unroll 1
    for (int t = 0; t < T_ENC; t++) {
        pa = *reinterpret_cast<const float4*>(poses + ((size_t)t * B + b0) * 4);
        pb = *reinterpret_cast<const float4*>(poses + ((size_t)t * B + b1c) * 4);
        lstm_step2(pack2(pa.x, pa.y), pack2(pa.z, pa.w),
                   pack2(pb.x, pb.y), pack2(pb.z, pb.w),
                   h2a, h2b, sWih, sWhh, sHnA, sHnB, sCa, sCb, tid);
    }
    float pxa = pa.x, pya = pa.y;   // last_pose[:, :2], constant in decoder
    float pxb = pb.x, pyb = pb.y;

    int Td = *n_new;
    if (Td > Tdec_max) Td = Tdec_max;

    // ---- Decoder ----
#pragma unroll 1
    for (int t = 0; t < Td; t++) {
        u64 aca = 0ull, asa = 0ull, acb = 0ull, asb = 0ull;
#pragma unroll
        for (int k2 = 0; k2 < 16; k2++) {
            ulonglong2 w = *reinterpret_cast<const ulonglong2*>(&sWd[k2]);
            aca = fma2(h2a[k2], w.x, aca);  acb = fma2(h2b[k2], w.x, acb);
            asa = fma2(h2a[k2], w.y, asa);  asb = fma2(h2b[k2], w.y, asb);
        }
        float csa = hsum2(aca), sna = hsum2(asa);
        float csb = hsum2(acb), snb = hsum2(asb);
        float rna, rnb;
        asm("rsqrt.approx.f32 %0, %1;" : "=f"(rna) : "f"(csa * csa + sna * sna));
        asm("rsqrt.approx.f32 %0, %1;" : "=f"(rnb) : "f"(csb * csb + snb * snb));
        csa *= rna; sna *= rna;
        csb *= rnb; snb *= rnb;

        *reinterpret_cast<float4*>(out + ((size_t)t * B + b0) * 4) =
            make_float4(pxa, pya, csa, sna);
        if (vb)
            *reinterpret_cast<float4*>(out + ((size_t)t * B + b1) * 4) =
                make_float4(pxb, pyb, csb, snb);

        if (t + 1 < Td) {  // last step's LSTM output is never consumed
            lstm_step2(pack2(pxa, pya), pack2(csa, sna),
                       pack2(pxb, pyb), pack2(csb, snb),
                       h2a, h2b, sWih, sWhh, sHnA, sHnB, sCa, sCb, tid);
        }
    }
}

extern "C" void kernel_launch(void* const* d_in, const int* in_sizes, int n_in,
                              void* d_out, int out_size) {
    const float* poses = (const float*)d_in[0];
    // d_in[1] = deltas: never read (the scan body ignores dt); only its length matters.
    const float* W_ih  = (const float*)d_in[2];
    const float* W_hh  = (const float*)d_in[3];
    const float* W_d   = (const float*)d_in[4];
    const int*   n_new = (const int*)d_in[5];
    float* out = (float*)d_out;

    int B = in_sizes[1] / 64;                      // deltas is [64, B]
    int Bh = (B + 1) / 2;                          // elements per "lane 0"
    int Tdec_max = (B > 0) ? (out_size / (4 * B)) : 0;

    static bool attr_set = false;
    if (!attr_set) {
        cudaFuncSetAttribute(dynamics_kernel,
                             cudaFuncAttributeMaxDynamicSharedMemorySize, SMEM_BYTES);
        attr_set = true;
    }

    int grid = (Bh + THREADS - 1) / THREADS;       // 256 for B=65536
    dynamics_kernel<<<grid, THREADS, SMEM_BYTES>>>(
        poses, W_ih, W_hh, W_d, n_new, out, B, Bh, Tdec_max);
}

// round 14
// speedup vs baseline: 1.1765x; 1.0067x over previous
#include <cuda_runtime.h>
#include <cuda_bf16.h>
#include <cstdint>

// Dynamics_40510131536026: LSTM encoder (T=64) + autoregressive decoder (T=64)
// B=65536, HID=32, fp32. Two batch elements per thread (weight LDS amortized),
// FFMA2 (fma.rn.f32x2) packed over K. R14: software-pipelined epilogue —
// iteration j issues the FMA/LDS block for gate-row j AND the activation
// epilogue for row j-1, so the serial MUFU chain hides under the next row's
// issue stream (R13 was latency-bound on the per-j epilogue tail:
// issue=47.6%, fma=48.6%). j loop stays unroll-1 (R11 lesson: full unroll ->
// ptxas load hoisting -> catastrophic spill).

#define THREADS 128
#define HID 32
#define T_ENC 64

typedef unsigned long long u64;

__device__ __forceinline__ u64 fma2(u64 a, u64 b, u64 c) {
    u64 d;
    asm("fma.rn.f32x2 %0, %1, %2, %3;" : "=l"(d) : "l"(a), "l"(b), "l"(c));
    return d;
}
__device__ __forceinline__ u64 pack2(float lo, float hi) {
    u64 r;
    asm("mov.b64 %0, {%1, %2};" : "=l"(r) : "f"(lo), "f"(hi));
    return r;
}
__device__ __forceinline__ float hsum2(u64 v) {
    float lo, hi;
    asm("mov.b64 {%0, %1}, %2;" : "=f"(lo), "=f"(hi) : "l"(v));
    return lo + hi;
}
__device__ __forceinline__ float sigm(float x) {
    return __fdividef(1.0f, 1.0f + __expf(-x));
}
__device__ __forceinline__ float tanhx(float x) {
    return __fdividef(2.0f, 1.0f + __expf(-2.0f * x)) - 1.0f;
}

// Dynamic smem layout:
//   sWhh : 32*16*2 float4 = 16384 B
//   sWih : 32*2*2  float4 =  2048 B
//   sWd  : 16      float4 =   256 B
//   sHnA/sHnB : 16*128 u64  = 16384 B each   (h_new staging, per-thread slot)
//   sCa/sCb   : 32*128 f32  = 16384 B each   (c state, per-thread slot)
#define SWHH_F4 (HID * 16 * 2)
#define SWIH_F4 (HID * 2 * 2)
#define SWD_F4  16
#define SMEM_BYTES ((SWHH_F4 + SWIH_F4 + SWD_F4) * 16 \
                    + 2 * 16 * THREADS * 8 + 2 * HID * THREADS * 4)

// FMA/LDS block for gate-row j, both elements. acc[0..3] = i,f,g,o for elem A,
// acc[4..7] for elem B.
__device__ __forceinline__ void fma_block(
    int j, u64 x0a, u64 x1a, u64 x0b, u64 x1b,
    const u64* __restrict__ h2a, const u64* __restrict__ h2b,
    const float4* __restrict__ sWih, const float4* __restrict__ sWhh,
    u64* __restrict__ acc)
{
    {   // x @ W_ih.T contribution (weights loaded once, used for both elems)
        ulonglong2 w0 = *reinterpret_cast<const ulonglong2*>(&sWih[(j * 2 + 0) * 2]);
        ulonglong2 w1 = *reinterpret_cast<const ulonglong2*>(&sWih[(j * 2 + 0) * 2 + 1]);
        acc[0] = fma2(x0a, w0.x, 0ull);  acc[4] = fma2(x0b, w0.x, 0ull);
        acc[1] = fma2(x0a, w0.y, 0ull);  acc[5] = fma2(x0b, w0.y, 0ull);
        acc[2] = fma2(x0a, w1.x, 0ull);  acc[6] = fma2(x0b, w1.x, 0ull);
        acc[3] = fma2(x0a, w1.y, 0ull);  acc[7] = fma2(x0b, w1.y, 0ull);
        w0 = *reinterpret_cast<const ulonglong2*>(&sWih[(j * 2 + 1) * 2]);
        w1 = *reinterpret_cast<const ulonglong2*>(&sWih[(j * 2 + 1) * 2 + 1]);
        acc[0] = fma2(x1a, w0.x, acc[0]);  acc[4] = fma2(x1b, w0.x, acc[4]);
        acc[1] = fma2(x1a, w0.y, acc[1]);  acc[5] = fma2(x1b, w0.y, acc[5]);
        acc[2] = fma2(x1a, w1.x, acc[2]);  acc[6] = fma2(x1b, w1.x, acc[6]);
        acc[3] = fma2(x1a, w1.y, acc[3]);  acc[7] = fma2(x1b, w1.y, acc[7]);
    }
    const float4* wrow = &sWhh[j * 16 * 2];
#pragma unroll
    for (int k2 = 0; k2 < 16; k2++) {
        ulonglong2 w0 = *reinterpret_cast<const ulonglong2*>(&wrow[k2 * 2]);
        ulonglong2 w1 = *reinterpret_cast<const ulonglong2*>(&wrow[k2 * 2 + 1]);
        u64 ha = h2a[k2];
        u64 hb = h2b[k2];
        acc[0] = fma2(ha, w0.x, acc[0]);  acc[4] = fma2(hb, w0.x, acc[4]);
        acc[1] = fma2(ha, w0.y, acc[1]);  acc[5] = fma2(hb, w0.y, acc[5]);
        acc[2] = fma2(ha, w1.x, acc[2]);  acc[6] = fma2(hb, w1.x, acc[6]);
        acc[3] = fma2(ha, w1.y, acc[3]);  acc[7] = fma2(hb, w1.y, acc[7]);
    }
}

// Activation epilogue for gate-row j, both elements (consumes acc of row j).
__device__ __forceinline__ void epi(
    int j, const u64* __restrict__ acc, float& hva, float& hvb,
    float* __restrict__ sCa, float* __restrict__ sCb,
    u64* __restrict__ sHnA, u64* __restrict__ sHnB, int tid)
{
    // Element A
    {
        float ii = sigm(hsum2(acc[0]));
        float ff = sigm(hsum2(acc[1]));
        float gg = tanhx(hsum2(acc[2]));
        float oo = sigm(hsum2(acc[3]));
        float cn = ff * sCa[j * THREADS + tid] + ii * gg;
        sCa[j * THREADS + tid] = cn;
        float hj = oo * tanhx(cn);
        if (j & 1) sHnA[(j >> 1) * THREADS + tid] = pack2(hva, hj);
        else       hva = hj;
    }
    // Element B
    {
        float ii = sigm(hsum2(acc[4]));
        float ff = sigm(hsum2(acc[5]));
        float gg = tanhx(hsum2(acc[6]));
        float oo = sigm(hsum2(acc[7]));
        float cn = ff * sCb[j * THREADS + tid] + ii * gg;
        sCb[j * THREADS + tid] = cn;
        float hj = oo * tanhx(cn);
        if (j & 1) sHnB[(j >> 1) * THREADS + tid] = pack2(hvb, hj);
        else       hvb = hj;
    }
}

// One LSTM step for two batch elements, software-pipelined: iteration j does
// fma_block(j) and epi(j-1) in one basic block so ptxas interleaves the
// independent streams.
__device__ __forceinline__ void lstm_step2(
    u64 x0a, u64 x1a, u64 x0b, u64 x1b,
    u64* __restrict__ h2a, u64* __restrict__ h2b,
    const float4* __restrict__ sWih, const float4* __restrict__ sWhh,
    u64* __restrict__ sHnA, u64* __restrict__ sHnB,
    float* __restrict__ sCa, float* __restrict__ sCb, int tid)
{
    float hva = 0.0f, hvb = 0.0f;
    u64 aP[8];
    fma_block(0, x0a, x1a, x0b, x1b, h2a, h2b, sWih, sWhh, aP);
#pragma unroll 1
    for (int j = 1; j < HID; j++) {
        u64 aN[8];
        fma_block(j, x0a, x1a, x0b, x1b, h2a, h2b, sWih, sWhh, aN);
        epi(j - 1, aP, hva, hvb, sCa, sCb, sHnA, sHnB, tid);
#pragma unroll
        for (int q = 0; q < 8; q++) aP[q] = aN[q];
    }
    epi(HID - 1, aP, hva, hvb, sCa, sCb, sHnA, sHnB, tid);

#pragma unroll
    for (int k2 = 0; k2 < 16; k2++) {
        h2a[k2] = sHnA[k2 * THREADS + tid];
        h2b[k2] = sHnB[k2 * THREADS + tid];
    }
}

__global__ __launch_bounds__(THREADS, 2)
void dynamics_kernel(
    const float* __restrict__ poses,   // [64, B, 4]
    const float* __restrict__ W_ih,    // [128, 4]
    const float* __restrict__ W_hh,    // [128, 32]
    const float* __restrict__ W_d,     // [3, 32]
    const int*   __restrict__ n_new,   // scalar
    float* __restrict__ out,           // [Tdec, B, 4]
    int B, int Bh, int Tdec_max)
{
    extern __shared__ char smem_raw[];
    float4* sWhh = reinterpret_cast<float4*>(smem_raw);
    float4* sWih = sWhh + SWHH_F4;
    float4* sWd  = sWih + SWIH_F4;
    u64*    sHnA = reinterpret_cast<u64*>(sWd + SWD_F4);
    u64*    sHnB = sHnA + 16 * THREADS;
    float*  sCa  = reinterpret_cast<float*>(sHnB + 16 * THREADS);
    float*  sCb  = sCa + HID * THREADS;

    int tid = threadIdx.x;

    // Cooperative weight packing.
    // sWhh[(j*16+k2)*2+e]: e=0 -> {Wi[j][k],Wi[j][k+1],Wf[j][k],Wf[j][k+1]},
    //                      e=1 -> {Wg..., Wo...}   (gate rows: i=0,f=1,g=2,o=3)
    for (int idx = tid; idx < SWHH_F4; idx += THREADS) {
        int e  = idx & 1;
        int k2 = (idx >> 1) & 15;
        int j  = idx >> 5;
        int g0 = 2 * e, g1 = 2 * e + 1;
        int k  = 2 * k2;
        sWhh[idx] = make_float4(
            W_hh[(g0 * HID + j) * HID + k], W_hh[(g0 * HID + j) * HID + k + 1],
            W_hh[(g1 * HID + j) * HID + k], W_hh[(g1 * HID + j) * HID + k + 1]);
    }
    for (int idx = tid; idx < SWIH_F4; idx += THREADS) {
        int e  = idx & 1;
        int m2 = (idx >> 1) & 1;
        int j  = idx >> 2;
        int g0 = 2 * e, g1 = 2 * e + 1;
        int m  = 2 * m2;
        sWih[idx] = make_float4(
            W_ih[(g0 * HID + j) * 4 + m], W_ih[(g0 * HID + j) * 4 + m + 1],
            W_ih[(g1 * HID + j) * 4 + m], W_ih[(g1 * HID + j) * 4 + m + 1]);
    }
    for (int idx = tid; idx < SWD_F4; idx += THREADS) {
        int k = 2 * idx;   // rows 1 (cs) and 2 (sn) of W_dense
        sWd[idx] = make_float4(W_d[HID + k], W_d[HID + k + 1],
                               W_d[2 * HID + k], W_d[2 * HID + k + 1]);
    }
    __syncthreads();

    int b0 = blockIdx.x * THREADS + tid;
    if (b0 >= Bh) return;
    int b1 = b0 + Bh;
    bool vb = (b1 < B);
    int b1c = vb ? b1 : b0;   // clamp: redundant compute, stores guarded

    u64 h2a[16], h2b[16];
#pragma unroll
    for (int k2 = 0; k2 < 16; k2++) { h2a[k2] = 0ull; h2b[k2] = 0ull; }
#pragma unroll
    for (int j = 0; j < HID; j++) {
        sCa[j * THREADS + tid] = 0.0f;
        sCb[j * THREADS + tid] = 0.0f;
    }

    // ---- Encoder: 64 steps over poses ----
    float4 pa = make_float4(0.f, 0.f, 0.f, 0.f);
    float4 pb = pa;
#pragma unroll 1
    for (int t = 0; t < T_ENC; t++) {
        pa = *reinterpret_cast<const float4*>(poses + ((size_t)t * B + b0) * 4);
        pb = *reinterpret_cast<const float4*>(poses + ((size_t)t * B + b1c) * 4);
        lstm_step2(pack2(pa.x, pa.y), pack2(pa.z, pa.w),
                   pack2(pb.x, pb.y), pack2(pb.z, pb.w),
                   h2a, h2b, sWih, sWhh, sHnA, sHnB, sCa, sCb, tid);
    }
    float pxa = pa.x, pya = pa.y;   // last_pose[:, :2], constant in decoder
    float pxb = pb.x, pyb = pb.y;

    int Td = *n_new;
    if (Td > Tdec_max) Td = Tdec_max;

    // ---- Decoder ----
#pragma unroll 1
    for (int t = 0; t < Td; t++) {
        u64 aca = 0ull, asa = 0ull, acb = 0ull, asb = 0ull;
#pragma unroll
        for (int k2 = 0; k2 < 16; k2++) {
            ulonglong2 w = *reinterpret_cast<const ulonglong2*>(&sWd[k2]);
            aca = fma2(h2a[k2], w.x, aca);  acb = fma2(h2b[k2], w.x, acb);
            asa = fma2(h2a[k2], w.y, asa);  asb = fma2(h2b[k2], w.y, asb);
        }
        float csa = hsum2(aca), sna = hsum2(asa);
        float csb = hsum2(acb), snb = hsum2(asb);
        float rna, rnb;
        asm("rsqrt.approx.f32 %0, %1;" : "=f"(rna) : "f"(csa * csa + sna * sna));
        asm("rsqrt.approx.f32 %0, %1;" : "=f"(rnb) : "f"(csb * csb + snb * snb));
        csa *= rna; sna *= rna;
        csb *= rnb; snb *= rnb;

        *reinterpret_cast<float4*>(out + ((size_t)t * B + b0) * 4) =
            make_float4(pxa, pya, csa, sna);
        if (vb)
            *reinterpret_cast<float4*>(out + ((size_t)t * B + b1) * 4) =
                make_float4(pxb, pyb, csb, snb);

        if (t + 1 < Td) {  // last step's LSTM output is never consumed
            lstm_step2(pack2(pxa, pya), pack2(csa, sna),
                       pack2(pxb, pyb), pack2(csb, snb),
                       h2a, h2b, sWih, sWhh, sHnA, sHnB, sCa, sCb, tid);
        }
    }
}

extern "C" void kernel_launch(void* const* d_in, const int* in_sizes, int n_in,
                              void* d_out, int out_size) {
    const float* poses = (const float*)d_in[0];
    // d_in[1] = deltas: never read (the scan body ignores dt); only its length matters.
    const float* W_ih  = (const float*)d_in[2];
    const float* W_hh  = (const float*)d_in[3];
    const float* W_d   = (const float*)d_in[4];
    const int*   n_new = (const int*)d_in[5];
    float* out = (float*)d_out;

    int B = in_sizes[1] / 64;                      // deltas is [64, B]
    int Bh = (B + 1) / 2;                          // elements per "lane 0"
    int Tdec_max = (B > 0) ? (out_size / (4 * B)) : 0;

    static bool attr_set = false;
    if (!attr_set) {
        cudaFuncSetAttribute(dynamics_kernel,
                             cudaFuncAttributeMaxDynamicSharedMemorySize, SMEM_BYTES);
        attr_set = true;
    }

    int grid = (Bh + THREADS - 1) / THREADS;       // 256 for B=65536
    dynamics_kernel<<<grid, THREADS, SMEM_BYTES>>>(
        poses, W_ih, W_hh, W_d, n_new, out, B, Bh, Tdec_max);
}